// round 11
// baseline (speedup 1.0000x reference)
#include <cuda_runtime.h>
#include <cuda_fp16.h>
#include <cstdint>

// Problem dims
#define BB 512
#define SS 512
#define II 256
#define HH 512
#define OO 256
#define G4 2048   // 4*HH, gate-interleaved: n = j*4 + gate, order (g,i,f,o)

#define PTHREADS 256
#define LTHREADS 512
#define NCTA 128    // 8 groups x 16 nt (128 gate-cols each)

// smem geometry (lstm kernel)
#define LDH 136                       // padded row stride (halfs) for A-chunks
#define HCHUNK_B (64 * LDH * 2)       // 17,408 B per chunk buffer
#define SWH_B (128 * 512 * 2)         // W4h slice, swizzled, 131,072 B
#define SWX_B (128 * 256 * 2)         // W4x slice, swizzled,  65,536 B
#define LSTM_SMEM (SWH_B + SWX_B + 2 * HCHUNK_B)   // 231,424 B <= 232,448

// ---------------- device-global scratch (no cudaMalloc) ----------------
__device__ __align__(16) __half g_W4x_h[(size_t)G4 * II];
__device__ __align__(16) __half g_W4h_h[(size_t)G4 * HH];
__device__ __align__(16) __half g_Wp_h[(size_t)OO * HH];
__device__ float  g_bias4[G4];
__device__ __align__(16) __half g_Xh[(size_t)BB * SS * II];  // x fp16 (128 MB)
__device__ __align__(16) __half g_Hh[2][(size_t)BB * HH];
__device__ unsigned g_sub[8 * 4 * 32];  // per-group, per-k-quarter counters, 128B apart
__device__ unsigned g_arrive;           // global barrier before projection

// ---------------- helpers ----------------
__device__ __forceinline__ float sigf(float x) {
    return __fdividef(1.f, 1.f + __expf(-x));
}
__device__ __forceinline__ float tanhfast(float x) {
    x = fminf(15.f, fmaxf(-15.f, x));
    float t = __expf(2.f * x);
    return __fdividef(t - 1.f, t + 1.f);
}
__device__ __forceinline__ void ldsm4(uint32_t* r, uint32_t addr) {
    asm volatile("ldmatrix.sync.aligned.m8n8.x4.shared.b16 {%0,%1,%2,%3}, [%4];"
                 : "=r"(r[0]), "=r"(r[1]), "=r"(r[2]), "=r"(r[3]) : "r"(addr));
}
__device__ __forceinline__ void mma16816(float* d, const uint32_t* a, const uint32_t* b) {
    asm volatile("mma.sync.aligned.m16n8k16.row.col.f32.f16.f16.f32 "
                 "{%0,%1,%2,%3},{%4,%5,%6,%7},{%8,%9},{%0,%1,%2,%3};"
                 : "+f"(d[0]), "+f"(d[1]), "+f"(d[2]), "+f"(d[3])
                 : "r"(a[0]), "r"(a[1]), "r"(a[2]), "r"(a[3]), "r"(b[0]), "r"(b[1]));
}
__device__ __forceinline__ void cpasync16(uint32_t dst, const void* src) {
    asm volatile("cp.async.cg.shared.global [%0], [%1], 16;" :: "r"(dst), "l"(src));
}
__device__ __forceinline__ void cpasync_commit() {
    asm volatile("cp.async.commit_group;" ::: "memory");
}
template <int N>
__device__ __forceinline__ void cpasync_waitg() {
    asm volatile("cp.async.wait_group %0;" :: "n"(N) : "memory");
}
__device__ __forceinline__ uint32_t smem_u32(const void* p) {
    return (uint32_t)__cvta_generic_to_shared(p);
}
#define SWZ128(b) ((b) ^ (((b) >> 3) & 0x70))

__device__ __forceinline__ void ctr_arrive(unsigned* ctr) {
    asm volatile("red.release.gpu.global.add.u32 [%0], 1;" :: "l"(ctr) : "memory");
}
__device__ __forceinline__ void ctr_wait(unsigned* ctr, unsigned target) {
    if (threadIdx.x == 0) {
        unsigned v;
        do {
            asm volatile("ld.acquire.gpu.global.u32 %0, [%1];" : "=r"(v) : "l"(ctr) : "memory");
        } while ((int)(v - target) < 0);
    }
    __syncthreads();
}
__device__ __forceinline__ void ctr_bar(unsigned* ctr, unsigned target) {
    __syncthreads();
    if (threadIdx.x == 0) ctr_arrive(ctr);
    ctr_wait(ctr, target);
}

// ---------------- kernel 1: pack weights fp16 gate-interleaved + reset barriers ----------------
__global__ void pack_kernel(
    const float* __restrict__ Wgx, const float* __restrict__ Wgh,
    const float* __restrict__ Wix, const float* __restrict__ Wih,
    const float* __restrict__ Wfx, const float* __restrict__ Wfh,
    const float* __restrict__ Wox, const float* __restrict__ Woh,
    const float* __restrict__ bgx, const float* __restrict__ bgh,
    const float* __restrict__ bix, const float* __restrict__ bih,
    const float* __restrict__ bfx, const float* __restrict__ bfh,
    const float* __restrict__ box_, const float* __restrict__ boh,
    const float* __restrict__ Wph)
{
    int idx = blockIdx.x * blockDim.x + threadIdx.x;  // covers G4*HH exactly
    if (idx < 8 * 4 * 32) g_sub[idx] = 0;
    if (idx == 0) g_arrive = 0;
    if (idx < G4 * HH) {
        int n = idx >> 9, k = idx & 511;
        int gate = n & 3, j = n >> 2;
        const float* W = (gate == 0) ? Wgh : (gate == 1) ? Wih : (gate == 2) ? Wfh : Woh;
        g_W4h_h[idx] = __float2half_rn(W[j * HH + k]);
    }
    if (idx < G4 * II) {
        int n = idx >> 8, k = idx & 255;
        int gate = n & 3, j = n >> 2;
        const float* W = (gate == 0) ? Wgx : (gate == 1) ? Wix : (gate == 2) ? Wfx : Wox;
        g_W4x_h[idx] = __float2half_rn(W[j * II + k]);
    }
    if (idx < G4) {
        int gate = idx & 3, j = idx >> 2;
        const float* bx = (gate == 0) ? bgx : (gate == 1) ? bix : (gate == 2) ? bfx : box_;
        const float* bh = (gate == 0) ? bgh : (gate == 1) ? bih : (gate == 2) ? bfh : boh;
        g_bias4[idx] = bx[j] + bh[j];
    }
    if (idx < OO * HH) {
        g_Wp_h[idx] = __float2half_rn(Wph[idx]);
    }
}

// ---------------- kernel 1b: convert x to fp16 ----------------
__global__ void xconv_kernel(const float* __restrict__ x) {
    size_t i = ((size_t)blockIdx.x * PTHREADS + threadIdx.x) * 8;
    float4 a = *reinterpret_cast<const float4*>(x + i);
    float4 b = *reinterpret_cast<const float4*>(x + i + 4);
    __half2 h0 = __floats2half2_rn(a.x, a.y);
    __half2 h1 = __floats2half2_rn(a.z, a.w);
    __half2 h2 = __floats2half2_rn(b.x, b.y);
    __half2 h3 = __floats2half2_rn(b.z, b.w);
    uint4 o;
    o.x = *reinterpret_cast<uint32_t*>(&h0);
    o.y = *reinterpret_cast<uint32_t*>(&h1);
    o.z = *reinterpret_cast<uint32_t*>(&h2);
    o.w = *reinterpret_cast<uint32_t*>(&h3);
    *reinterpret_cast<uint4*>(g_Xh + i) = o;
}

// ---------------- lstm device helpers ----------------
// Load a 128-row x KD-half W slice into SW128-swizzled smem panels (16KB per 64-half panel).
template <int KD>
__device__ __forceinline__ void load_Wsw(uint32_t sdst, const __half* gsrc, int tid) {
#pragma unroll
    for (int i = 0; i < (128 * KD / 8) / LTHREADS; i++) {
        int id = i * LTHREADS + tid;
        int row = id / (KD / 8);
        int c8 = (id % (KD / 8)) * 8;                 // half offset within row
        uint32_t off = ((uint32_t)(c8 >> 6) << 14) + SWZ128((uint32_t)(row * 128 + (c8 & 63) * 2));
        cpasync16(sdst + off, gsrc + (size_t)row * KD + c8);
    }
}

// x chunk: 64 rows x 128 halfs of x[b0.., s, kbase..] into padded buffer
__device__ __forceinline__ void load_xchunk(uint32_t sdst, int b0, int s, int kbase, int tid) {
#pragma unroll
    for (int i = 0; i < 2; i++) {
        int id = i * LTHREADS + tid;
        int row = id >> 4;
        int c8 = (id & 15) * 8;
        cpasync16(sdst + (row * LDH + c8) * 2,
                  g_Xh + ((size_t)(b0 + row) * SS + s) * II + kbase + c8);
    }
}
// h chunk: 64 rows x 128 halfs of h[b0.., kbase..]
__device__ __forceinline__ void load_hchunk(uint32_t sdst, const __half* hsrc, int kbase, int tid) {
#pragma unroll
    for (int i = 0; i < 2; i++) {
        int id = i * LTHREADS + tid;
        int row = id >> 4;
        int c8 = (id & 15) * 8;
        cpasync16(sdst + (row * LDH + c8) * 2, hsrc + (size_t)row * HH + kbase + c8);
    }
}

// One k=128 chunk: A from padded buffer, B from swizzled W panels at global k = kglob+kk.
__device__ __forceinline__ void gemm_chunkW(float (&acc)[4][4], uint32_t aAddr,
                                            uint32_t bOff0, uint32_t bOff1,
                                            uint32_t sWb, int kglob) {
#pragma unroll
    for (int kk = 0; kk < 128; kk += 16) {
        int kg = kglob + kk;
        uint32_t pan = sWb + ((uint32_t)(kg >> 6) << 14);
        uint32_t kx = (uint32_t)((kg & 63) * 2);
        uint32_t a[4], b[2][4];
        ldsm4(a, aAddr + kk * 2);
        ldsm4(b[0], pan + (bOff0 ^ kx));
        ldsm4(b[1], pan + (bOff1 ^ kx));
#pragma unroll
        for (int ni = 0; ni < 4; ni++)
            mma16816(acc[ni], a, b[ni >> 1] + (ni & 1) * 2);
    }
}

__device__ __forceinline__ void do_stage(float* stg, const float (&acc)[4][4],
                                         const float (&bv)[4][2],
                                         int m0w, int n0w, int gq, int t4) {
#pragma unroll
    for (int ni = 0; ni < 4; ni++) {
        int r = m0w + gq;
        int c = n0w + ni * 8 + t4 * 2;
        stg[r * 132 + c]           = acc[ni][0] + bv[ni][0];
        stg[r * 132 + c + 1]       = acc[ni][1] + bv[ni][1];
        stg[(r + 8) * 132 + c]     = acc[ni][2] + bv[ni][0];
        stg[(r + 8) * 132 + c + 1] = acc[ni][3] + bv[ni][1];
    }
}

// gates: 64 rows x 32 h-cols per CTA; 512 threads -> thread owns (row, 4 h-cols); C in regs
__device__ __forceinline__ void do_gates(const float* stg, int tid, __half* hdst,
                                         int b0, int nt, float (&C)[4], bool first) {
    int bl = tid >> 3;
    int j4 = tid & 7;
    __half hv[4];
#pragma unroll
    for (int jj = 0; jj < 4; jj++) {
        float4 v = *reinterpret_cast<const float4*>(stg + bl * 132 + j4 * 16 + jj * 4);
        float gg = tanhfast(v.x), iv = sigf(v.y), fv = sigf(v.z), ov = sigf(v.w);
        C[jj] = first ? gg * iv : fmaf(C[jj], fv, gg * iv);
        hv[jj] = __float2half_rn(tanhfast(C[jj]) * ov);
    }
    *reinterpret_cast<uint2*>(hdst + (size_t)(b0 + bl) * HH + nt * 32 + j4 * 4) =
        *reinterpret_cast<uint2*>(hv);
}

// ---------------- kernel 2: fused persistent loop (x-proj folded into K) ----------------
__global__ void __launch_bounds__(LTHREADS, 1) lstm_kernel(const float* __restrict__ bph,
                                                           float* __restrict__ out) {
    extern __shared__ __align__(16) char dsm[];
    const uint32_t sm0 = smem_u32(dsm);
    const uint32_t sWh = sm0;                       // swizzled W4h slice
    const uint32_t sWx = sm0 + SWH_B;               // swizzled W4x slice
    const uint32_t buf0 = sm0 + SWH_B + SWX_B;      // A-chunk buffers (padded LDH)
    const uint32_t buf1 = buf0 + HCHUNK_B;
    float* stg = (float*)(dsm + SWH_B + SWX_B);     // stage 64x132 f32 spans both buffers

    const int tid = threadIdx.x;
    const int cta = blockIdx.x;
    const int nt  = cta & 15;    // 128 gate-cols -> 32 h-cols owned
    const int grp = cta >> 4;    // 0..7
    const int b0  = grp * 64;
    const int n0  = nt * 128;
    const int myq = nt >> 2;     // k-quarter this CTA's h-cols belong to
    unsigned* sub = &g_sub[grp * 4 * 32];
    unsigned* myctr = sub + myq * 32;

    // resident weight slices (one commit group)
    load_Wsw<512>(sWh, g_W4h_h + (size_t)n0 * HH, tid);
    load_Wsw<256>(sWx, g_W4x_h + (size_t)n0 * II, tid);
    cpasync_commit();

    const int lane = tid & 31, warp = tid >> 5;
    const int m0w = (warp >> 2) * 16;   // 4m x 4n warp grid, warp tile 16x32
    const int n0w = (warp & 3) * 32;
    const int lg = lane >> 3, rl = lane & 7;
    const int gq = lane >> 2, t4 = lane & 3;
    // A fragment lane address (padded chunk buffers)
    const uint32_t aOff = ((m0w + (lg & 1) * 8 + rl) * LDH + (lg >> 1) * 8) * 2;
    const uint32_t aAddr[2] = { buf0 + aOff, buf1 + aOff };
    // B fragment lane offsets (swizzled panels): off = row*128 ^ ((row&7)<<4) ^ (lg&1)*16
    uint32_t bOff[2];
#pragma unroll
    for (int nj = 0; nj < 2; nj++) {
        int row = n0w + nj * 16 + (lg >> 1) * 8 + rl;
        bOff[nj] = ((uint32_t)(row * 128) ^ ((uint32_t)(row & 7) << 4)) ^ (uint32_t)((lg & 1) * 16);
    }
    // bias registers (constant across steps)
    float bv[4][2];
#pragma unroll
    for (int ni = 0; ni < 4; ni++) {
        int c = n0 + n0w + ni * 8 + t4 * 2;
        bv[ni][0] = g_bias4[c];
        bv[ni][1] = g_bias4[c + 1];
    }

    float C[4];

    for (int s = 0; s < SS; ++s) {
        float acc[4][4] = {};

        // ---- x part of K (no barrier needed) ----
        load_xchunk(buf0, b0, s, 0, tid);   cpasync_commit();
        load_xchunk(buf1, b0, s, 128, tid); cpasync_commit();
        cpasync_waitg<1>(); __syncthreads();
        gemm_chunkW(acc, aAddr[0], bOff[0], bOff[1], sWx, 0);

        if (s == 0) {
            cpasync_waitg<0>(); __syncthreads();
            gemm_chunkW(acc, aAddr[1], bOff[0], bOff[1], sWx, 128);
        } else {
            const __half* hsrc = g_Hh[s & 1] + (size_t)b0 * HH;
            const unsigned tgt = (unsigned)s * 4;

            ctr_wait(sub + 0 * 32, tgt);                    // h k[0:128) published
            load_hchunk(buf0, hsrc, 0, tid); cpasync_commit();
            cpasync_waitg<1>(); __syncthreads();
            gemm_chunkW(acc, aAddr[1], bOff[0], bOff[1], sWx, 128);  // x k[128:256)

            ctr_wait(sub + 1 * 32, tgt);
            load_hchunk(buf1, hsrc, 128, tid); cpasync_commit();
            cpasync_waitg<1>(); __syncthreads();
            gemm_chunkW(acc, aAddr[0], bOff[0], bOff[1], sWh, 0);    // h k[0:128)

            ctr_wait(sub + 2 * 32, tgt);
            load_hchunk(buf0, hsrc, 256, tid); cpasync_commit();
            cpasync_waitg<1>(); __syncthreads();
            gemm_chunkW(acc, aAddr[1], bOff[0], bOff[1], sWh, 128);

            ctr_wait(sub + 3 * 32, tgt);
            load_hchunk(buf1, hsrc, 384, tid); cpasync_commit();
            cpasync_waitg<1>(); __syncthreads();
            gemm_chunkW(acc, aAddr[0], bOff[0], bOff[1], sWh, 256);

            cpasync_waitg<0>(); __syncthreads();
            gemm_chunkW(acc, aAddr[1], bOff[0], bOff[1], sWh, 384);
        }

        __syncthreads();   // all chunk readers done before stage overwrites buffer region
        do_stage(stg, acc, bv, m0w, n0w, gq, t4);
        __syncthreads();
        do_gates(stg, tid, g_Hh[(s + 1) & 1], b0, nt, C, s == 0);
        __syncthreads();   // h stores by all threads ordered before tid0's release
        if (tid == 0) ctr_arrive(myctr);
    }

    // ---- global barrier, then final projection (h(512) in g_Hh[0]) ----
    ctr_bar(&g_arrive, NCTA);

    if (cta < 16) {
        const int pb0 = (cta >> 1) * 64;   // 8 row tiles
        const int pn0 = (cta & 1) * 128;   // 2 col tiles
        // reload sWh with Wp slice (128 out-cols x 512)
        load_Wsw<512>(sWh, g_Wp_h + (size_t)pn0 * HH, tid);
        cpasync_commit();
        cpasync_waitg<0>(); __syncthreads();

        const __half* hs = g_Hh[0] + (size_t)pb0 * HH;
        float acc[4][4] = {};
        load_hchunk(buf0, hs, 0, tid);   cpasync_commit();
        load_hchunk(buf1, hs, 128, tid); cpasync_commit();
        cpasync_waitg<1>(); __syncthreads();
        gemm_chunkW(acc, aAddr[0], bOff[0], bOff[1], sWh, 0);
        __syncthreads();
        load_hchunk(buf0, hs, 256, tid); cpasync_commit();
        cpasync_waitg<1>(); __syncthreads();
        gemm_chunkW(acc, aAddr[1], bOff[0], bOff[1], sWh, 128);
        __syncthreads();
        load_hchunk(buf1, hs, 384, tid); cpasync_commit();
        cpasync_waitg<1>(); __syncthreads();
        gemm_chunkW(acc, aAddr[0], bOff[0], bOff[1], sWh, 256);
        cpasync_waitg<0>(); __syncthreads();
        gemm_chunkW(acc, aAddr[1], bOff[0], bOff[1], sWh, 384);

#pragma unroll
        for (int ni = 0; ni < 4; ni++) {
            int r  = m0w + gq;
            int cl = pn0 + n0w + ni * 8 + t4 * 2;
            float b0v = bph[cl], b1v = bph[cl + 1];
            out[(size_t)(pb0 + r) * OO + cl]         = acc[ni][0] + b0v;
            out[(size_t)(pb0 + r) * OO + cl + 1]     = acc[ni][1] + b1v;
            out[(size_t)(pb0 + r + 8) * OO + cl]     = acc[ni][2] + b0v;
            out[(size_t)(pb0 + r + 8) * OO + cl + 1] = acc[ni][3] + b1v;
        }
    }
}

// ---------------- launch ----------------
extern "C" void kernel_launch(void* const* d_in, const int* in_sizes, int n_in,
                              void* d_out, int out_size) {
    (void)in_sizes; (void)n_in; (void)out_size;
    const float* x   = (const float*)d_in[0];
    const float* Wgx = (const float*)d_in[1];
    const float* bgx = (const float*)d_in[2];
    const float* Wgh = (const float*)d_in[3];
    const float* bgh = (const float*)d_in[4];
    const float* Wix = (const float*)d_in[5];
    const float* bix = (const float*)d_in[6];
    const float* Wih = (const float*)d_in[7];
    const float* bih = (const float*)d_in[8];
    const float* Wfx = (const float*)d_in[9];
    const float* bfx = (const float*)d_in[10];
    const float* Wfh = (const float*)d_in[11];
    const float* bfh = (const float*)d_in[12];
    const float* Wox = (const float*)d_in[13];
    const float* box_ = (const float*)d_in[14];
    const float* Woh = (const float*)d_in[15];
    const float* boh = (const float*)d_in[16];
    const float* Wph = (const float*)d_in[17];
    const float* bph = (const float*)d_in[18];

    cudaFuncSetAttribute((const void*)lstm_kernel,
                         cudaFuncAttributeMaxDynamicSharedMemorySize, LSTM_SMEM);

    pack_kernel<<<(G4 * HH) / PTHREADS, PTHREADS>>>(
        Wgx, Wgh, Wix, Wih, Wfx, Wfh, Wox, Woh,
        bgx, bgh, bix, bih, bfx, bfh, box_, boh, Wph);

    xconv_kernel<<<(BB * SS * II) / (PTHREADS * 8), PTHREADS>>>(x);

    lstm_kernel<<<NCTA, LTHREADS, LSTM_SMEM>>>(bph, (float*)d_out);
}

// round 13
// speedup vs baseline: 1.0924x; 1.0924x over previous
#include <cuda_runtime.h>
#include <cuda_fp16.h>
#include <cstdint>

// Problem dims
#define BB 512
#define SS 512
#define II 256
#define HH 512
#define OO 256
#define G4 2048   // 4*HH, gate-interleaved: n = j*4 + gate, order (g,i,f,o)

#define PTHREADS 256
#define LTHREADS 256
#define NCTA 256    // 8 groups x 32 nt (64 gate-cols each)

// smem geometry (lstm kernel): 2 CTAs/SM
#define LDH 136                     // padded row stride (halfs) for A-chunk
#define BUF_B (64 * LDH * 2)        // 17,408 B single chunk buffer
#define SWH_B (64 * 512 * 2)        // W4h slice, swizzled, 65,536 B
#define SWX_B (64 * 256 * 2)        // W4x slice, swizzled, 32,768 B
#define LSTM_SMEM (SWH_B + SWX_B + BUF_B)   // 115,712 B -> 2/SM

// ---------------- device-global scratch (no cudaMalloc) ----------------
__device__ __align__(16) __half g_W4x_h[(size_t)G4 * II];
__device__ __align__(16) __half g_W4h_h[(size_t)G4 * HH];
__device__ __align__(16) __half g_Wp_h[(size_t)OO * HH];
__device__ float  g_bias4[G4];
__device__ __align__(16) __half g_Xh[(size_t)BB * SS * II];  // x fp16 (128 MB)
__device__ __align__(16) __half g_Hh[2][(size_t)BB * HH];
__device__ unsigned g_sub[8 * 4 * 32];  // per-group, per-k-quarter counters, 128B apart
__device__ unsigned g_arrive;           // global barrier before projection

// ---------------- helpers ----------------
__device__ __forceinline__ float sigf(float x) {
    return __fdividef(1.f, 1.f + __expf(-x));
}
__device__ __forceinline__ float tanhfast(float x) {
    x = fminf(15.f, fmaxf(-15.f, x));
    float t = __expf(2.f * x);
    return __fdividef(t - 1.f, t + 1.f);
}
__device__ __forceinline__ void ldsm4(uint32_t* r, uint32_t addr) {
    asm volatile("ldmatrix.sync.aligned.m8n8.x4.shared.b16 {%0,%1,%2,%3}, [%4];"
                 : "=r"(r[0]), "=r"(r[1]), "=r"(r[2]), "=r"(r[3]) : "r"(addr));
}
__device__ __forceinline__ void mma16816(float* d, const uint32_t* a, const uint32_t* b) {
    asm volatile("mma.sync.aligned.m16n8k16.row.col.f32.f16.f16.f32 "
                 "{%0,%1,%2,%3},{%4,%5,%6,%7},{%8,%9},{%0,%1,%2,%3};"
                 : "+f"(d[0]), "+f"(d[1]), "+f"(d[2]), "+f"(d[3])
                 : "r"(a[0]), "r"(a[1]), "r"(a[2]), "r"(a[3]), "r"(b[0]), "r"(b[1]));
}
__device__ __forceinline__ void cpasync16(uint32_t dst, const void* src) {
    asm volatile("cp.async.cg.shared.global [%0], [%1], 16;" :: "r"(dst), "l"(src));
}
__device__ __forceinline__ void cpasync_commit() {
    asm volatile("cp.async.commit_group;" ::: "memory");
}
template <int N>
__device__ __forceinline__ void cpasync_waitg() {
    asm volatile("cp.async.wait_group %0;" :: "n"(N) : "memory");
}
__device__ __forceinline__ uint32_t smem_u32(const void* p) {
    return (uint32_t)__cvta_generic_to_shared(p);
}
#define SWZ128(b) ((b) ^ (((b) >> 3) & 0x70))

__device__ __forceinline__ void ctr_arrive(unsigned* ctr) {
    asm volatile("red.release.gpu.global.add.u32 [%0], 1;" :: "l"(ctr) : "memory");
}
__device__ __forceinline__ void ctr_wait(unsigned* ctr, unsigned target) {
    if (threadIdx.x == 0) {
        unsigned v;
        while (true) {
            asm volatile("ld.acquire.gpu.global.u32 %0, [%1];" : "=r"(v) : "l"(ctr) : "memory");
            if ((int)(v - target) >= 0) break;
            __nanosleep(32);
        }
    }
    __syncthreads();
}
__device__ __forceinline__ void ctr_bar(unsigned* ctr, unsigned target) {
    __syncthreads();
    if (threadIdx.x == 0) ctr_arrive(ctr);
    ctr_wait(ctr, target);
}

// ---------------- kernel 1: pack weights fp16 gate-interleaved + reset barriers ----------------
__global__ void pack_kernel(
    const float* __restrict__ Wgx, const float* __restrict__ Wgh,
    const float* __restrict__ Wix, const float* __restrict__ Wih,
    const float* __restrict__ Wfx, const float* __restrict__ Wfh,
    const float* __restrict__ Wox, const float* __restrict__ Woh,
    const float* __restrict__ bgx, const float* __restrict__ bgh,
    const float* __restrict__ bix, const float* __restrict__ bih,
    const float* __restrict__ bfx, const float* __restrict__ bfh,
    const float* __restrict__ box_, const float* __restrict__ boh,
    const float* __restrict__ Wph)
{
    int idx = blockIdx.x * blockDim.x + threadIdx.x;  // covers G4*HH exactly
    if (idx < 8 * 4 * 32) g_sub[idx] = 0;
    if (idx == 0) g_arrive = 0;
    if (idx < G4 * HH) {
        int n = idx >> 9, k = idx & 511;
        int gate = n & 3, j = n >> 2;
        const float* W = (gate == 0) ? Wgh : (gate == 1) ? Wih : (gate == 2) ? Wfh : Woh;
        g_W4h_h[idx] = __float2half_rn(W[j * HH + k]);
    }
    if (idx < G4 * II) {
        int n = idx >> 8, k = idx & 255;
        int gate = n & 3, j = n >> 2;
        const float* W = (gate == 0) ? Wgx : (gate == 1) ? Wix : (gate == 2) ? Wfx : Wox;
        g_W4x_h[idx] = __float2half_rn(W[j * II + k]);
    }
    if (idx < G4) {
        int gate = idx & 3, j = idx >> 2;
        const float* bx = (gate == 0) ? bgx : (gate == 1) ? bix : (gate == 2) ? bfx : box_;
        const float* bh = (gate == 0) ? bgh : (gate == 1) ? bih : (gate == 2) ? bfh : boh;
        g_bias4[idx] = bx[j] + bh[j];
    }
    if (idx < OO * HH) {
        g_Wp_h[idx] = __float2half_rn(Wph[idx]);
    }
}

// ---------------- kernel 1b: convert x to fp16 ----------------
__global__ void xconv_kernel(const float* __restrict__ x) {
    size_t i = ((size_t)blockIdx.x * PTHREADS + threadIdx.x) * 8;
    float4 a = *reinterpret_cast<const float4*>(x + i);
    float4 b = *reinterpret_cast<const float4*>(x + i + 4);
    __half2 h0 = __floats2half2_rn(a.x, a.y);
    __half2 h1 = __floats2half2_rn(a.z, a.w);
    __half2 h2 = __floats2half2_rn(b.x, b.y);
    __half2 h3 = __floats2half2_rn(b.z, b.w);
    uint4 o;
    o.x = *reinterpret_cast<uint32_t*>(&h0);
    o.y = *reinterpret_cast<uint32_t*>(&h1);
    o.z = *reinterpret_cast<uint32_t*>(&h2);
    o.w = *reinterpret_cast<uint32_t*>(&h3);
    *reinterpret_cast<uint4*>(g_Xh + i) = o;
}

// ---------------- lstm device helpers ----------------
// Load a 64-row x KD-half W slice into SW128-swizzled smem panels (8KB per 64-half panel).
template <int KD>
__device__ __forceinline__ void load_Wsw(uint32_t sdst, const __half* gsrc, int tid) {
#pragma unroll
    for (int i = 0; i < (64 * KD / 8) / LTHREADS; i++) {
        int id = i * LTHREADS + tid;
        int row = id / (KD / 8);
        int c8 = (id % (KD / 8)) * 8;
        uint32_t off = ((uint32_t)(c8 >> 6) << 13) + SWZ128((uint32_t)(row * 128 + (c8 & 63) * 2));
        cpasync16(sdst + off, gsrc + (size_t)row * KD + c8);
    }
}

// x chunk: 64 rows x 128 halfs into padded buffer
__device__ __forceinline__ void load_xchunk(uint32_t sdst, int b0, int s, int kbase, int tid) {
#pragma unroll
    for (int i = 0; i < 4; i++) {
        int id = i * LTHREADS + tid;
        int row = id >> 4;
        int c8 = (id & 15) * 8;
        cpasync16(sdst + (row * LDH + c8) * 2,
                  g_Xh + ((size_t)(b0 + row) * SS + s) * II + kbase + c8);
    }
}
// h chunk: 64 rows x 128 halfs
__device__ __forceinline__ void load_hchunk(uint32_t sdst, const __half* hsrc, int kbase, int tid) {
#pragma unroll
    for (int i = 0; i < 4; i++) {
        int id = i * LTHREADS + tid;
        int row = id >> 4;
        int c8 = (id & 15) * 8;
        cpasync16(sdst + (row * LDH + c8) * 2, hsrc + (size_t)row * HH + kbase + c8);
    }
}

// One k=128 chunk: A from padded buffer, B from swizzled 64-row W panels at k=kglob+kk.
__device__ __forceinline__ void gemm_chunkW(float (&acc)[4][4], uint32_t aAddr,
                                            uint32_t bOff0, uint32_t bOff1,
                                            uint32_t sWb, int kglob) {
#pragma unroll
    for (int kk = 0; kk < 128; kk += 16) {
        int kg = kglob + kk;
        uint32_t pan = sWb + ((uint32_t)(kg >> 6) << 13);
        uint32_t kx = (uint32_t)((kg & 63) * 2);
        uint32_t a[4], b[2][4];
        ldsm4(a, aAddr + kk * 2);
        ldsm4(b[0], pan + (bOff0 ^ kx));
        ldsm4(b[1], pan + (bOff1 ^ kx));
#pragma unroll
        for (int ni = 0; ni < 4; ni++)
            mma16816(acc[ni], a, b[ni >> 1] + (ni & 1) * 2);
    }
}

// ---------------- kernel 2: fused persistent loop, 64 gate-cols/CTA, 2 CTAs/SM ----------------
__global__ void __launch_bounds__(LTHREADS, 2) lstm_kernel(const float* __restrict__ bph,
                                                           float* __restrict__ out) {
    extern __shared__ __align__(16) char dsm[];
    const uint32_t sm0 = smem_u32(dsm);
    const uint32_t sWh = sm0;                  // swizzled W4h slice (8 panels)
    const uint32_t sWx = sm0 + SWH_B;          // swizzled W4x slice (4 panels)
    const uint32_t buf = sm0 + SWH_B + SWX_B;  // single A-chunk buffer (padded LDH)

    const int tid = threadIdx.x;
    const int cta = blockIdx.x;
    const int nt  = cta & 31;    // 64 gate-cols -> 16 h-cols owned
    const int grp = cta >> 5;    // 0..7
    const int b0  = grp * 64;
    const int n0  = nt * 64;
    const int myq = nt >> 3;     // k-quarter this CTA's h-cols belong to (8 CTAs/quarter)
    unsigned* sub = &g_sub[grp * 4 * 32];
    unsigned* myctr = sub + myq * 32;

    // resident weight slices + first x chunk (one commit group)
    load_Wsw<512>(sWh, g_W4h_h + (size_t)n0 * HH, tid);
    load_Wsw<256>(sWx, g_W4x_h + (size_t)n0 * II, tid);
    load_xchunk(buf, b0, 0, 0, tid);
    cpasync_commit();

    const int lane = tid & 31, warp = tid >> 5;
    const int m0w = (warp >> 1) * 16;   // 4m x 2n warp grid, warp tile 16x32
    const int n0w = (warp & 1) * 32;
    const int lg = lane >> 3, rl = lane & 7;
    const int gq = lane >> 2, t4 = lane & 3;
    const uint32_t aAddr = buf + ((m0w + (lg & 1) * 8 + rl) * LDH + (lg >> 1) * 8) * 2;
    uint32_t bOff[2];
#pragma unroll
    for (int nj = 0; nj < 2; nj++) {
        int row = n0w + nj * 16 + (lg >> 1) * 8 + rl;
        bOff[nj] = ((uint32_t)(row * 128) ^ ((uint32_t)(row & 7) << 4)) ^ (uint32_t)((lg & 1) * 16);
    }
    float bv[4][2];
#pragma unroll
    for (int ni = 0; ni < 4; ni++) {
        int c = n0 + n0w + ni * 8 + t4 * 2;
        bv[ni][0] = g_bias4[c];
        bv[ni][1] = g_bias4[c + 1];
    }

    const bool oddl = (t4 & 1);
    float C[4];

    for (int s = 0; s < SS; ++s) {
        float acc[4][4] = {};

        // x k[0:128)  (prefetched at end of previous step / prologue)
        cpasync_waitg<0>(); __syncthreads();
        gemm_chunkW(acc, aAddr, bOff[0], bOff[1], sWx, 0);
        __syncthreads();
        load_xchunk(buf, b0, s, 128, tid); cpasync_commit();
        if (s > 0) ctr_wait(sub + 0 * 32, (unsigned)s * 8);   // overlaps x1 load
        cpasync_waitg<0>(); __syncthreads();
        gemm_chunkW(acc, aAddr, bOff[0], bOff[1], sWx, 128);

        if (s > 0) {
            const __half* hsrc = g_Hh[s & 1] + (size_t)b0 * HH;
            const unsigned tgt = (unsigned)s * 8;
            __syncthreads();
            load_hchunk(buf, hsrc, 0, tid); cpasync_commit();
            ctr_wait(sub + 1 * 32, tgt);                      // overlaps h0 load
            cpasync_waitg<0>(); __syncthreads();
            gemm_chunkW(acc, aAddr, bOff[0], bOff[1], sWh, 0);
            __syncthreads();
            load_hchunk(buf, hsrc, 128, tid); cpasync_commit();
            ctr_wait(sub + 2 * 32, tgt);
            cpasync_waitg<0>(); __syncthreads();
            gemm_chunkW(acc, aAddr, bOff[0], bOff[1], sWh, 128);
            __syncthreads();
            load_hchunk(buf, hsrc, 256, tid); cpasync_commit();
            ctr_wait(sub + 3 * 32, tgt);
            cpasync_waitg<0>(); __syncthreads();
            gemm_chunkW(acc, aAddr, bOff[0], bOff[1], sWh, 256);
            __syncthreads();
            load_hchunk(buf, hsrc, 384, tid); cpasync_commit();
            cpasync_waitg<0>(); __syncthreads();
            gemm_chunkW(acc, aAddr, bOff[0], bOff[1], sWh, 384);
        }

        __syncthreads();   // all warps done reading buf
        if (s + 1 < SS) {  // prefetch next step's x0 under epilogue + arrive + q0 wait
            load_xchunk(buf, b0, s + 1, 0, tid); cpasync_commit();
        }

        // ---- shuffle-fused gate epilogue (no smem stage) ----
        __half* hdst = g_Hh[(s + 1) & 1];
        const bool first = (s == 0);
#pragma unroll
        for (int ni = 0; ni < 4; ni++) {
            float v0 = acc[ni][0] + bv[ni][0];
            float v1 = acc[ni][1] + bv[ni][1];
            float v2 = acc[ni][2] + bv[ni][0];
            float v3 = acc[ni][3] + bv[ni][1];
            float x0s = __shfl_xor_sync(0xFFFFFFFFu, v0, 1);
            float x1s = __shfl_xor_sync(0xFFFFFFFFu, v1, 1);
            float x2s = __shfl_xor_sync(0xFFFFFFFFu, v2, 1);
            float x3s = __shfl_xor_sync(0xFFFFFFFFu, v3, 1);
            float gv = oddl ? x2s : v0;
            float iv = oddl ? x3s : v1;
            float fv = oddl ? v2 : x0s;
            float ov = oddl ? v3 : x1s;
            float gg = tanhfast(gv), is = sigf(iv), fs = sigf(fv), os = sigf(ov);
            C[ni] = first ? gg * is : fmaf(C[ni], fs, gg * is);
            float h = tanhfast(C[ni]) * os;
            int row = m0w + gq + (oddl ? 8 : 0);
            int jloc = (n0w >> 2) + ni * 2 + (t4 >> 1);
            hdst[(size_t)(b0 + row) * HH + nt * 16 + jloc] = __float2half_rn(h);
        }

        __syncthreads();   // h stores by all threads ordered before tid0's release
        if (tid == 0) ctr_arrive(myctr);
    }

    // ---- global barrier, then final projection (h(512) in g_Hh[0]) ----
    ctr_bar(&g_arrive, NCTA);

    if (cta < 32) {
        const int pb0 = (cta >> 2) * 64;   // 8 row tiles
        const int pn0 = (cta & 3) * 64;    // 4 col tiles
        load_Wsw<512>(sWh, g_Wp_h + (size_t)pn0 * HH, tid);
        cpasync_commit();
        const __half* hs = g_Hh[0] + (size_t)pb0 * HH;
        float acc[4][4] = {};
#pragma unroll
        for (int c = 0; c < 4; c++) {
            load_hchunk(buf, hs, c * 128, tid); cpasync_commit();
            cpasync_waitg<0>(); __syncthreads();
            gemm_chunkW(acc, aAddr, bOff[0], bOff[1], sWh, c * 128);
            __syncthreads();
        }
#pragma unroll
        for (int ni = 0; ni < 4; ni++) {
            int r  = m0w + gq;
            int cl = pn0 + n0w + ni * 8 + t4 * 2;
            float b0v = bph[cl], b1v = bph[cl + 1];
            out[(size_t)(pb0 + r) * OO + cl]         = acc[ni][0] + b0v;
            out[(size_t)(pb0 + r) * OO + cl + 1]     = acc[ni][1] + b1v;
            out[(size_t)(pb0 + r + 8) * OO + cl]     = acc[ni][2] + b0v;
            out[(size_t)(pb0 + r + 8) * OO + cl + 1] = acc[ni][3] + b1v;
        }
    }
}

// ---------------- launch ----------------
extern "C" void kernel_launch(void* const* d_in, const int* in_sizes, int n_in,
                              void* d_out, int out_size) {
    (void)in_sizes; (void)n_in; (void)out_size;
    const float* x   = (const float*)d_in[0];
    const float* Wgx = (const float*)d_in[1];
    const float* bgx = (const float*)d_in[2];
    const float* Wgh = (const float*)d_in[3];
    const float* bgh = (const float*)d_in[4];
    const float* Wix = (const float*)d_in[5];
    const float* bix = (const float*)d_in[6];
    const float* Wih = (const float*)d_in[7];
    const float* bih = (const float*)d_in[8];
    const float* Wfx = (const float*)d_in[9];
    const float* bfx = (const float*)d_in[10];
    const float* Wfh = (const float*)d_in[11];
    const float* bfh = (const float*)d_in[12];
    const float* Wox = (const float*)d_in[13];
    const float* box_ = (const float*)d_in[14];
    const float* Woh = (const float*)d_in[15];
    const float* boh = (const float*)d_in[16];
    const float* Wph = (const float*)d_in[17];
    const float* bph = (const float*)d_in[18];

    cudaFuncSetAttribute((const void*)lstm_kernel,
                         cudaFuncAttributeMaxDynamicSharedMemorySize, LSTM_SMEM);

    pack_kernel<<<(G4 * HH) / PTHREADS, PTHREADS>>>(
        Wgx, Wgh, Wix, Wih, Wfx, Wfh, Wox, Woh,
        bgx, bgh, bix, bih, bfx, bfh, box_, boh, Wph);

    xconv_kernel<<<(BB * SS * II) / (PTHREADS * 8), PTHREADS>>>(x);

    lstm_kernel<<<NCTA, LTHREADS, LSTM_SMEM>>>(bph, (float*)d_out);
}